// round 13
// baseline (speedup 1.0000x reference)
#include <cuda_runtime.h>
#include <math.h>

#define T 8
#define N 20000
#define E 1280000
#define TN (T*N)
#define NGRP (E/8)              // 160000 8-edge groups

#define TAILN  1280
#define CHUNKS 64
#define CLEN   20               // CHUNKS*CLEN == TAILN ; multiple of 4
#define WARM   640              // proven-safe warmup (multiple of 4)
#define KEEP   (TAILN + WARM)   // 1920 tail nodes of graph 7 need u
#define NODE0  (N - KEEP)       // 18080

#define GRID 148                // one block per SM: co-residency needs only occupancy>=1
#define BLK  512
#define NTHR (GRID*BLK)

#define K_SCALE 2.8853900817779268f   // 2*log2(e)

// ---- cheap-path scratch (graph 7 only); self-cleaning across graph replays ----
__device__ float    d_xl[N*2];        // xl (fully overwritten each launch)
__device__ int      d_cnt4[4*N];      // 4-replica degree counts (zeroed by cleanup blocks)
__device__ float    d_acc4[4*KEEP*2]; // 4-replica tail accumulator (zeroed by cleanup blocks)
__device__ float    d_u0[KEEP], d_u1[KEEP], d_u2[KEEP];  // U = K*(u + rowsum(Whh))
__device__ unsigned g_bar;            // barrier counter: 0 at launch start & end
__device__ int      d_sink;           // prefetch sink (never meaningfully written)

// ---- fallback scratch (full problem; zeroed at fallback start) ----
__device__ int    f_cnt[TN];
__device__ float2 f_p[TN];
__device__ float  f_acc[TN*2];
__device__ float  f_u[TN*3];

__device__ __forceinline__ int cnt_of(int n) {
    return d_cnt4[n] + d_cnt4[N + n] + d_cnt4[2*N + n] + d_cnt4[3*N + n];
}

__device__ __forceinline__ void red2(float* p, float a, float b) {
    asm volatile("red.global.add.v2.f32 [%0], {%1, %2};"
                 :: "l"(p), "f"(a), "f"(b) : "memory");
}

// One block per SM -> all blocks resident -> monotonic counter barrier is safe.
__device__ __forceinline__ void grid_bar(unsigned target) {
    __syncthreads();
    if (threadIdx.x == 0) {
        __threadfence();
        atomicAdd(&g_bar, 1u);
        while (*(volatile unsigned*)&g_bar < target) __nanosleep(32);
        __threadfence();
    }
    __syncthreads();
}

// ---------------- scan helpers (r-space: r = (1-h)/2, h = 1-2r) ----------------
#define STEPR(c0, c1, c2) { \
    float A0 = fmaf(m00,r0, fmaf(m01,r1, fmaf(m02,r2, (c0)))); \
    float A1 = fmaf(m10,r0, fmaf(m11,r1, fmaf(m12,r2, (c1)))); \
    float A2 = fmaf(m20,r0, fmaf(m21,r1, fmaf(m22,r2, (c2)))); \
    float e0, e1, e2, q0, q1, q2; \
    asm("ex2.approx.f32 %0, %1;" : "=f"(e0) : "f"(A0)); \
    asm("ex2.approx.f32 %0, %1;" : "=f"(e1) : "f"(A1)); \
    asm("ex2.approx.f32 %0, %1;" : "=f"(e2) : "f"(A2)); \
    e0 += 1.0f; e1 += 1.0f; e2 += 1.0f; \
    asm("rcp.approx.f32 %0, %1;" : "=f"(q0) : "f"(e0)); \
    asm("rcp.approx.f32 %0, %1;" : "=f"(q1) : "f"(e1)); \
    asm("rcp.approx.f32 %0, %1;" : "=f"(q2) : "f"(e2)); \
    r0 = q0; r1 = q1; r2 = q2; }

#define QUADR(k) { \
    float4 a = *reinterpret_cast<const float4*>(d_u0 + (k)); \
    float4 b = *reinterpret_cast<const float4*>(d_u1 + (k)); \
    float4 u = *reinterpret_cast<const float4*>(d_u2 + (k)); \
    STEPR(a.x, b.x, u.x); STEPR(a.y, b.y, u.y); \
    STEPR(a.z, b.z, u.z); STEPR(a.w, b.w, u.w); }

// fallback step (unscaled, exact formulation)
__device__ __forceinline__ float tanh_fast(float x) {
    float e = __expf(2.0f * x);
    return 1.0f - __fdividef(2.0f, e + 1.0f);
}
#define STEPM(c0, c1, c2) { \
    float a0 = fmaf(v00,h0, fmaf(v01,h1, fmaf(v02,h2, (c0)))); \
    float a1 = fmaf(v10,h0, fmaf(v11,h1, fmaf(v12,h2, (c1)))); \
    float a2 = fmaf(v20,h0, fmaf(v21,h1, fmaf(v22,h2, (c2)))); \
    h0 = tanh_fast(a0); h1 = tanh_fast(a1); h2 = tanh_fast(a2); }

__global__ void __launch_bounds__(BLK)
k_all(const float* __restrict__ x, const int* __restrict__ ei,
      const float* __restrict__ Wg, const float* __restrict__ bg,
      const float* __restrict__ Wih, const float* __restrict__ Whh,
      const float* __restrict__ bih, const float* __restrict__ bhh,
      const float* __restrict__ Wlin, const float* __restrict__ blin,
      float* __restrict__ out) {
    int tid = threadIdx.x, bid = blockIdx.x;
    int gtid = bid * BLK + tid;
    const int* eit = ei + (size_t)7*2*E;

    // ---- P1: xl + 4-replica degree histogram; prefetch src into L2 ----
    for (int n = gtid; n < N; n += NTHR) {
        float x0 = x[2*(7*N + n)], x1 = x[2*(7*N + n) + 1];
        d_xl[2*n]   = fmaf(x0, Wg[0], x1 * Wg[1]);
        d_xl[2*n+1] = fmaf(x0, Wg[2], x1 * Wg[3]);
    }
    {
        int rep = (tid & 3) * N;
        int pf = 0;
        for (int g = gtid; g < NGRP; g += NTHR) {
            int4 a = *reinterpret_cast<const int4*>(eit + E + 8*g);
            int4 c = *reinterpret_cast<const int4*>(eit + E + 8*g + 4);
            // prefetch src halves into L2 for P2 (values folded into pf, kept alive)
            int4 pa = *reinterpret_cast<const int4*>(eit + 8*g);
            int4 pb = *reinterpret_cast<const int4*>(eit + 8*g + 4);
            pf ^= pa.x ^ pa.y ^ pa.z ^ pa.w ^ pb.x ^ pb.y ^ pb.z ^ pb.w;
            atomicAdd(&d_cnt4[rep + a.x], 1); atomicAdd(&d_cnt4[rep + a.y], 1);
            atomicAdd(&d_cnt4[rep + a.z], 1); atomicAdd(&d_cnt4[rep + a.w], 1);
            atomicAdd(&d_cnt4[rep + c.x], 1); atomicAdd(&d_cnt4[rep + c.y], 1);
            atomicAdd(&d_cnt4[rep + c.z], 1); atomicAdd(&d_cnt4[rep + c.w], 1);
        }
        if (pf == 0x5A5A5A5A) d_sink = pf;   // keep prefetch loads alive (deterministic)
    }
    grid_bar(GRID);                          // -> 148

    // ---- P2: messages into the tail (L2-warm reads; dinv[src] inline) ----
    {
        int rep = (tid & 3) * (KEEP*2);
        for (int g = gtid; g < NGRP; g += NTHR) {
            int4 s0 = *reinterpret_cast<const int4*>(eit + 8*g);
            int4 s1 = *reinterpret_cast<const int4*>(eit + 8*g + 4);
            int4 t0 = *reinterpret_cast<const int4*>(eit + E + 8*g);
            int4 t1 = *reinterpret_cast<const int4*>(eit + E + 8*g + 4);
            #define EDGE(S, D) if ((D) >= NODE0) { \
                float di = rsqrtf((float)(cnt_of(S) + 1)); \
                float2 xl = *reinterpret_cast<const float2*>(d_xl + 2*(S)); \
                red2(d_acc4 + rep + 2*((D) - NODE0), di*xl.x, di*xl.y); }
            EDGE(s0.x, t0.x) EDGE(s0.y, t0.y) EDGE(s0.z, t0.z) EDGE(s0.w, t0.w)
            EDGE(s1.x, t1.x) EDGE(s1.y, t1.y) EDGE(s1.z, t1.z) EDGE(s1.w, t1.w)
            #undef EDGE
        }
    }
    grid_bar(2u*GRID);                       // -> 296

    if (bid != 0) {
        // wait for block 0's u-prep tick (297), then clean scratch and exit
        if (tid == 0) {
            while (*(volatile unsigned*)&g_bar < 2u*GRID + 1u) __nanosleep(32);
            __threadfence();
        }
        __syncthreads();
        for (int i = (bid-1)*BLK + tid; i < 4*N;      i += (GRID-1)*BLK) d_cnt4[i] = 0;
        for (int i = (bid-1)*BLK + tid; i < 4*KEEP*2; i += (GRID-1)*BLK) d_acc4[i] = 0.f;
        __syncthreads();
        if (tid == 0) { __threadfence(); atomicAdd(&g_bar, 1u); }   // 298..444
        if (bid == 1 && tid == 0) {
            while (*(volatile unsigned*)&g_bar < 2u*GRID + 1u + (GRID-1u)) __nanosleep(32);
            *(volatile unsigned*)&g_bar = 0u;   // counter back to 0 for next launch
            __threadfence();
        }
        return;
    }

    // ================= block 0: u-prep + scan + gate + output =================
    {
        float wg0=Wih[0], wg1=Wih[1], wg2=Wih[2], wg3=Wih[3], wg4=Wih[4], wg5=Wih[5];
        float rs0 = Whh[0]+Whh[1]+Whh[2], rs1 = Whh[3]+Whh[4]+Whh[5], rs2 = Whh[6]+Whh[7]+Whh[8];
        float c0 = bih[0] + bhh[0] + rs0, c1 = bih[1] + bhh[1] + rs1, c2 = bih[2] + bhh[2] + rs2;
        float bg0 = bg[0], bg1 = bg[1];
        for (int i = tid; i < KEEP; i += BLK) {
            int n = NODE0 + i;
            float dinv = rsqrtf((float)(cnt_of(n) + 1));
            float2 xl = *reinterpret_cast<const float2*>(d_xl + 2*n);
            float a0 = d_acc4[2*i]            + d_acc4[KEEP*2 + 2*i]
                     + d_acc4[2*KEEP*2 + 2*i] + d_acc4[3*KEEP*2 + 2*i];
            float a1 = d_acc4[2*i+1]            + d_acc4[KEEP*2 + 2*i+1]
                     + d_acc4[2*KEEP*2 + 2*i+1] + d_acc4[3*KEEP*2 + 2*i+1];
            float g0 = fmaf(dinv, fmaf(dinv, xl.x, a0), bg0);
            float g1 = fmaf(dinv, fmaf(dinv, xl.y, a1), bg1);
            d_u0[i] = K_SCALE * fmaf(wg0, g0, fmaf(wg1, g1, c0));
            d_u1[i] = K_SCALE * fmaf(wg2, g0, fmaf(wg3, g1, c1));
            d_u2[i] = K_SCALE * fmaf(wg4, g0, fmaf(wg5, g1, c2));
        }
    }
    __syncthreads();
    if (tid == 0) { __threadfence(); atomicAdd(&g_bar, 1u); }   // -> 297: cleanup may start
    __syncthreads();

    __shared__ float s_s[CHUNKS+2][3], s_b[CHUNKS][3];   // stored as h
    __shared__ int s_ok;

    if (tid < CHUNKS + 2) {
        float m00=-2.f*K_SCALE*Whh[0], m01=-2.f*K_SCALE*Whh[1], m02=-2.f*K_SCALE*Whh[2];
        float m10=-2.f*K_SCALE*Whh[3], m11=-2.f*K_SCALE*Whh[4], m12=-2.f*K_SCALE*Whh[5];
        float m20=-2.f*K_SCALE*Whh[6], m21=-2.f*K_SCALE*Whh[7], m22=-2.f*K_SCALE*Whh[8];
        int c = (tid < CHUNKS) ? tid : 0;
        int ws = c * CLEN;                 // multiple of 4
        int k0 = ws + WARM;
        // h=0 -> r=0.5 ; h=+1 -> r=0 ; h=-1 -> r=1
        float init = (tid == CHUNKS) ? 0.f : (tid == CHUNKS+1 ? 1.f : 0.5f);
        float r0 = init, r1 = init, r2 = init;
        for (int k = ws; k < k0; k += 4) QUADR(k);
        s_s[tid][0] = fmaf(-2.f, r0, 1.f);
        s_s[tid][1] = fmaf(-2.f, r1, 1.f);
        s_s[tid][2] = fmaf(-2.f, r2, 1.f);
        if (tid < CHUNKS) {
            #pragma unroll 5
            for (int k = k0; k < k0 + CLEN; k += 4) QUADR(k);
            s_b[tid][0] = fmaf(-2.f, r0, 1.f);
            s_b[tid][1] = fmaf(-2.f, r1, 1.f);
            s_b[tid][2] = fmaf(-2.f, r2, 1.f);
        }
    }
    __syncthreads();

    if (tid == 0) {
        float md = 0.f;
        for (int c = 1; c < CHUNKS; c++)
            for (int m = 0; m < 3; m++)
                md = fmaxf(md, fabsf(s_s[c][m] - s_b[c-1][m]));
        for (int m = 0; m < 3; m++) {               // entrance insensitivity
            md = fmaxf(md, fabsf(s_s[CHUNKS][m]   - s_s[0][m]));
            md = fmaxf(md, fabsf(s_s[CHUNKS+1][m] - s_s[0][m]));
        }
        s_ok = (md < 2e-5f);
        if (s_ok) {
            float h0 = fmaxf(s_b[CHUNKS-1][0], 0.f);
            float h1 = fmaxf(s_b[CHUNKS-1][1], 0.f);
            float h2 = fmaxf(s_b[CHUNKS-1][2], 0.f);
            float z = fmaf(Wlin[0], h0, fmaf(Wlin[1], h1, fmaf(Wlin[2], h2, blin[0])));
            out[0] = 1.0f / (1.0f + expf(-z));
        }
    }
    __syncthreads();
    if (s_ok) return;

    // ================= FALLBACK: exact full computation (block 0) =================
    int nt = BLK;
    float v00=Whh[0], v01=Whh[1], v02=Whh[2];
    float v10=Whh[3], v11=Whh[4], v12=Whh[5];
    float v20=Whh[6], v21=Whh[7], v22=Whh[8];
    for (int g = tid; g < TN; g += nt) { f_cnt[g] = 0; f_acc[2*g] = 0.f; f_acc[2*g+1] = 0.f; }
    __syncthreads();
    for (long i = tid; i < (long)T*E; i += nt) {
        int t = (int)(i / E), e = (int)(i - (long)t*E);
        int dst = ei[(size_t)t*2*E + E + e];
        atomicAdd(&f_cnt[t*N + dst], 1);
    }
    __syncthreads();
    for (int g = tid; g < TN; g += nt) {
        float x0 = x[2*g], x1 = x[2*g+1];
        float xl0 = fmaf(x0, Wg[0], x1*Wg[1]);
        float xl1 = fmaf(x0, Wg[2], x1*Wg[3]);
        float dinv = rsqrtf((float)(f_cnt[g] + 1));
        f_p[g] = make_float2(dinv * xl0, dinv * xl1);
    }
    __syncthreads();
    for (long i = tid; i < (long)T*E; i += nt) {
        int t = (int)(i / E), e = (int)(i - (long)t*E);
        const int* et2 = ei + (size_t)t*2*E;
        int src = et2[e], dst = et2[E + e];
        float2 p = f_p[t*N + src];
        atomicAdd(&f_acc[2*(t*N + dst)],   p.x);
        atomicAdd(&f_acc[2*(t*N + dst)+1], p.y);
    }
    __syncthreads();
    for (int g = tid; g < TN; g += nt) {
        float dinv = rsqrtf((float)(f_cnt[g] + 1));
        float2 p = f_p[g];
        float g0 = fmaf(dinv, f_acc[2*g]   + p.x, bg[0]);
        float g1 = fmaf(dinv, f_acc[2*g+1] + p.y, bg[1]);
        f_u[3*g]   = fmaf(Wih[0], g0, fmaf(Wih[1], g1, bih[0] + bhh[0]));
        f_u[3*g+1] = fmaf(Wih[2], g0, fmaf(Wih[3], g1, bih[1] + bhh[1]));
        f_u[3*g+2] = fmaf(Wih[4], g0, fmaf(Wih[5], g1, bih[2] + bhh[2]));
    }
    __syncthreads();
    for (int g = tid; g < TN; g += nt) { f_cnt[g] = 0; f_acc[2*g] = 0.f; f_acc[2*g+1] = 0.f; }
    __syncthreads();
    if (tid == 0) {
        float h0 = 0.f, h1 = 0.f, h2 = 0.f;
        for (int k = 0; k < TN; k++) STEPM(f_u[3*k], f_u[3*k+1], f_u[3*k+2]);
        h0 = fmaxf(h0, 0.f); h1 = fmaxf(h1, 0.f); h2 = fmaxf(h2, 0.f);
        float z = fmaf(Wlin[0], h0, fmaf(Wlin[1], h1, fmaf(Wlin[2], h2, blin[0])));
        out[0] = 1.0f / (1.0f + expf(-z));
    }
}

extern "C" void kernel_launch(void* const* d_in, const int* in_sizes, int n_in,
                              void* d_out, int out_size) {
    const float* x    = (const float*)d_in[0];
    const int*   ei   = (const int*)  d_in[1];   // int32
    const float* Wg   = (const float*)d_in[2];
    const float* bg   = (const float*)d_in[3];
    const float* Wih  = (const float*)d_in[4];
    const float* Whh  = (const float*)d_in[5];
    const float* bih  = (const float*)d_in[6];
    const float* bhh  = (const float*)d_in[7];
    const float* Wlin = (const float*)d_in[8];
    const float* blin = (const float*)d_in[9];
    float* out = (float*)d_out;

    k_all<<<GRID, BLK>>>(x, ei, Wg, bg, Wih, Whh, bih, bhh, Wlin, blin, out);
}

// round 14
// speedup vs baseline: 1.5008x; 1.5008x over previous
#include <cuda_runtime.h>
#include <math.h>

#define T 8
#define N 20000
#define E 1280000
#define TN (T*N)

#define TAILN  1280
#define CHUNKS 64
#define CLEN   20          // CHUNKS*CLEN == TAILN ; multiple of 4
#define WARMA  320         // tier-A warmup (multiple of 4)
#define WARMB  640         // tier-B warmup, proven safe (multiple of 4)
#define KEEP   (TAILN + WARMB)  // 1920 tail nodes of graph 7 need u
#define NODE0  (N - KEEP)       // 18080

#define K_SCALE 2.8853900817779268f   // 2*log2(e)

#define XL_BLOCKS  ((N + 255) / 256)   // 79
#define DEG_BLOCKS (E/8/256)           // 625 (exact)

// ---- cheap-path scratch (graph 7 only); self-cleaning across graph replays ----
__device__ float  d_xl[N*2];      // xl (fully overwritten each launch)
__device__ int    d_cnt4[4*N];    // 4-replica degree counts (zeroed in k_finish)
__device__ float  d_acc[KEEP*2];  // tail accumulator (zeroed in k_finish)
__device__ float  d_u0[KEEP], d_u1[KEEP], d_u2[KEEP];  // U = K*(u + rowsum(Whh))

// ---- fallback scratch (full problem; zeroed at fallback start) ----
__device__ int    f_cnt[TN];
__device__ float2 f_p[TN];
__device__ float  f_acc[TN*2];
__device__ float  f_u[TN*3];

__device__ __forceinline__ int cnt_of(int n) {
    return d_cnt4[n] + d_cnt4[N + n] + d_cnt4[2*N + n] + d_cnt4[3*N + n];
}

// ---------------- graph-7 xl + replicated degree histogram (fused) ----------------
__global__ void k_deg7(const float* __restrict__ x, const float* __restrict__ Wg,
                       const int* __restrict__ ei) {
    int b = blockIdx.x;
    if (b < XL_BLOCKS) {
        int n = b * 256 + threadIdx.x;
        if (n >= N) return;
        float x0 = x[2*(7*N + n)], x1 = x[2*(7*N + n) + 1];
        d_xl[2*n]   = fmaf(x0, Wg[0], x1 * Wg[1]);
        d_xl[2*n+1] = fmaf(x0, Wg[2], x1 * Wg[3]);
    } else {
        int idx = (b - XL_BLOCKS) * 256 + threadIdx.x;   // < E/8 exactly
        int rep = (threadIdx.x & 3) * N;                 // replica base
        const int* dp = ei + (size_t)7*2*E + E + 8*idx;
        int4 a = *reinterpret_cast<const int4*>(dp);
        int4 c = *reinterpret_cast<const int4*>(dp + 4);
        atomicAdd(&d_cnt4[rep + a.x], 1); atomicAdd(&d_cnt4[rep + a.y], 1);
        atomicAdd(&d_cnt4[rep + a.z], 1); atomicAdd(&d_cnt4[rep + a.w], 1);
        atomicAdd(&d_cnt4[rep + c.x], 1); atomicAdd(&d_cnt4[rep + c.y], 1);
        atomicAdd(&d_cnt4[rep + c.z], 1); atomicAdd(&d_cnt4[rep + c.w], 1);
    }
}

// ---------------- messages into the tail; dinv[src] from merged replicas ----------------
__device__ __forceinline__ void red2(float* p, float a, float b) {
    asm volatile("red.global.add.v2.f32 [%0], {%1, %2};"
                 :: "l"(p), "f"(a), "f"(b) : "memory");
}

__global__ void k_msg7(const int* __restrict__ ei) {
    int idx = blockIdx.x * blockDim.x + threadIdx.x;    // < E/8 exactly
    const int* eit = ei + (size_t)7*2*E;
    int4 s0 = *reinterpret_cast<const int4*>(eit + 8*idx);
    int4 s1 = *reinterpret_cast<const int4*>(eit + 8*idx + 4);
    int4 t0 = *reinterpret_cast<const int4*>(eit + E + 8*idx);
    int4 t1 = *reinterpret_cast<const int4*>(eit + E + 8*idx + 4);
    #define EDGE(S, D) if ((D) >= NODE0) { \
        float di = rsqrtf((float)(cnt_of(S) + 1)); \
        float2 xl = *reinterpret_cast<const float2*>(d_xl + 2*(S)); \
        red2(d_acc + 2*((D) - NODE0), di*xl.x, di*xl.y); }
    EDGE(s0.x, t0.x) EDGE(s0.y, t0.y) EDGE(s0.z, t0.z) EDGE(s0.w, t0.w)
    EDGE(s1.x, t1.x) EDGE(s1.y, t1.y) EDGE(s1.z, t1.z) EDGE(s1.w, t1.w)
    #undef EDGE
}

// ---------------- scan helpers (r-space: r = (1-h)/2, h = 1-2r) ----------------
// r' = rcp(ex2(A)+1), A = U + m00*r0 + m01*r1 + m02*r2 ; m = -2*K_SCALE*Whh
#define STEPR(c0, c1, c2) { \
    float A0 = fmaf(m00,r0, fmaf(m01,r1, fmaf(m02,r2, (c0)))); \
    float A1 = fmaf(m10,r0, fmaf(m11,r1, fmaf(m12,r2, (c1)))); \
    float A2 = fmaf(m20,r0, fmaf(m21,r1, fmaf(m22,r2, (c2)))); \
    float e0, e1, e2, q0, q1, q2; \
    asm("ex2.approx.f32 %0, %1;" : "=f"(e0) : "f"(A0)); \
    asm("ex2.approx.f32 %0, %1;" : "=f"(e1) : "f"(A1)); \
    asm("ex2.approx.f32 %0, %1;" : "=f"(e2) : "f"(A2)); \
    e0 += 1.0f; e1 += 1.0f; e2 += 1.0f; \
    asm("rcp.approx.f32 %0, %1;" : "=f"(q0) : "f"(e0)); \
    asm("rcp.approx.f32 %0, %1;" : "=f"(q1) : "f"(e1)); \
    asm("rcp.approx.f32 %0, %1;" : "=f"(q2) : "f"(e2)); \
    r0 = q0; r1 = q1; r2 = q2; }

#define QUADR(k) { \
    float4 a = *reinterpret_cast<const float4*>(d_u0 + (k)); \
    float4 b = *reinterpret_cast<const float4*>(d_u1 + (k)); \
    float4 u = *reinterpret_cast<const float4*>(d_u2 + (k)); \
    STEPR(a.x, b.x, u.x); STEPR(a.y, b.y, u.y); \
    STEPR(a.z, b.z, u.z); STEPR(a.w, b.w, u.w); }

// fallback step (unscaled, exact formulation)
__device__ __forceinline__ float tanh_fast(float x) {
    float e = __expf(2.0f * x);
    return 1.0f - __fdividef(2.0f, e + 1.0f);
}
#define STEPM(c0, c1, c2) { \
    float a0 = fmaf(v00,h0, fmaf(v01,h1, fmaf(v02,h2, (c0)))); \
    float a1 = fmaf(v10,h0, fmaf(v11,h1, fmaf(v12,h2, (c1)))); \
    float a2 = fmaf(v20,h0, fmaf(v21,h1, fmaf(v22,h2, (c2)))); \
    h0 = tanh_fast(a0); h1 = tanh_fast(a1); h2 = tanh_fast(a2); }

// ---------------- u-prep + two-tier scan + gate + output (+ full fallback) ----------------
__global__ void k_finish(const float* __restrict__ x, const int* __restrict__ ei,
                         const float* __restrict__ Wg, const float* __restrict__ bg,
                         const float* __restrict__ Wih, const float* __restrict__ Whh,
                         const float* __restrict__ bih, const float* __restrict__ bhh,
                         const float* __restrict__ Wlin, const float* __restrict__ blin,
                         float* __restrict__ out) {
    __shared__ float s_s[CHUNKS+2][3], s_b[CHUNKS][3];   // stored as h
    __shared__ int s_ok;
    int tid = threadIdx.x;
    int nt = blockDim.x;

    // ---- phase A: U = K_SCALE*(u + rowsum(Whh)) for the tail nodes ----
    {
        float wg0=Wih[0], wg1=Wih[1], wg2=Wih[2], wg3=Wih[3], wg4=Wih[4], wg5=Wih[5];
        float rs0 = Whh[0]+Whh[1]+Whh[2], rs1 = Whh[3]+Whh[4]+Whh[5], rs2 = Whh[6]+Whh[7]+Whh[8];
        float c0 = bih[0] + bhh[0] + rs0, c1 = bih[1] + bhh[1] + rs1, c2 = bih[2] + bhh[2] + rs2;
        float bg0 = bg[0], bg1 = bg[1];
        for (int i = tid; i < KEEP; i += nt) {
            int n = NODE0 + i;
            float dinv = rsqrtf((float)(cnt_of(n) + 1));
            float2 xl = *reinterpret_cast<const float2*>(d_xl + 2*n);
            float g0 = fmaf(dinv, fmaf(dinv, xl.x, d_acc[2*i]),   bg0);
            float g1 = fmaf(dinv, fmaf(dinv, xl.y, d_acc[2*i+1]), bg1);
            d_u0[i] = K_SCALE * fmaf(wg0, g0, fmaf(wg1, g1, c0));
            d_u1[i] = K_SCALE * fmaf(wg2, g0, fmaf(wg3, g1, c1));
            d_u2[i] = K_SCALE * fmaf(wg4, g0, fmaf(wg5, g1, c2));
        }
    }
    __syncthreads();

    // ---- phase B: two-tier chunk scan; tier 0 uses WARMA, tier 1 WARMB ----
    float m00=-2.f*K_SCALE*Whh[0], m01=-2.f*K_SCALE*Whh[1], m02=-2.f*K_SCALE*Whh[2];
    float m10=-2.f*K_SCALE*Whh[3], m11=-2.f*K_SCALE*Whh[4], m12=-2.f*K_SCALE*Whh[5];
    float m20=-2.f*K_SCALE*Whh[6], m21=-2.f*K_SCALE*Whh[7], m22=-2.f*K_SCALE*Whh[8];

    for (int tier = 0; tier < 2; tier++) {
        int warm = (tier == 0) ? WARMA : WARMB;
        if (tid < CHUNKS + 2) {
            int c = (tid < CHUNKS) ? tid : 0;
            int k0 = WARMB + c * CLEN;      // chunk entry (fixed grid, multiple of 4)
            int ws = k0 - warm;             // multiple of 4
            // h=0 -> r=0.5 ; h=+1 -> r=0 ; h=-1 -> r=1
            float init = (tid == CHUNKS) ? 0.f : (tid == CHUNKS+1 ? 1.f : 0.5f);
            float r0 = init, r1 = init, r2 = init;
            for (int k = ws; k < k0; k += 4) QUADR(k);
            s_s[tid][0] = fmaf(-2.f, r0, 1.f);
            s_s[tid][1] = fmaf(-2.f, r1, 1.f);
            s_s[tid][2] = fmaf(-2.f, r2, 1.f);
            if (tid < CHUNKS) {
                #pragma unroll 5
                for (int k = k0; k < k0 + CLEN; k += 4) QUADR(k);
                s_b[tid][0] = fmaf(-2.f, r0, 1.f);
                s_b[tid][1] = fmaf(-2.f, r1, 1.f);
                s_b[tid][2] = fmaf(-2.f, r2, 1.f);
            }
        } else if (tid >= 128 && tier == 0) {
            // self-clean scratch, hidden under the tier-0 scan
            int t2 = tid - 128, n2 = nt - 128;
            for (int g = t2; g < 4*N;    g += n2) d_cnt4[g] = 0;
            for (int g = t2; g < KEEP*2; g += n2) d_acc[g] = 0.f;
        }
        __syncthreads();

        if (tid == 0) {
            float md = 0.f;
            for (int c = 1; c < CHUNKS; c++)
                for (int m = 0; m < 3; m++)
                    md = fmaxf(md, fabsf(s_s[c][m] - s_b[c-1][m]));
            for (int m = 0; m < 3; m++) {           // entrance insensitivity
                md = fmaxf(md, fabsf(s_s[CHUNKS][m]   - s_s[0][m]));
                md = fmaxf(md, fabsf(s_s[CHUNKS+1][m] - s_s[0][m]));
            }
            s_ok = (md < 2e-5f);
            if (s_ok) {
                float h0 = fmaxf(s_b[CHUNKS-1][0], 0.f);
                float h1 = fmaxf(s_b[CHUNKS-1][1], 0.f);
                float h2 = fmaxf(s_b[CHUNKS-1][2], 0.f);
                float z = fmaf(Wlin[0], h0, fmaf(Wlin[1], h1, fmaf(Wlin[2], h2, blin[0])));
                out[0] = 1.0f / (1.0f + expf(-z));
            }
        }
        __syncthreads();
        if (s_ok) return;
    }

    // ================= FALLBACK: exact full computation =================
    float v00=Whh[0], v01=Whh[1], v02=Whh[2];
    float v10=Whh[3], v11=Whh[4], v12=Whh[5];
    float v20=Whh[6], v21=Whh[7], v22=Whh[8];
    for (int g = tid; g < TN; g += nt) { f_cnt[g] = 0; f_acc[2*g] = 0.f; f_acc[2*g+1] = 0.f; }
    __syncthreads();
    for (long i = tid; i < (long)T*E; i += nt) {
        int t = (int)(i / E), e = (int)(i - (long)t*E);
        int dst = ei[(size_t)t*2*E + E + e];
        atomicAdd(&f_cnt[t*N + dst], 1);
    }
    __syncthreads();
    for (int g = tid; g < TN; g += nt) {
        float x0 = x[2*g], x1 = x[2*g+1];
        float xl0 = fmaf(x0, Wg[0], x1*Wg[1]);
        float xl1 = fmaf(x0, Wg[2], x1*Wg[3]);
        float dinv = rsqrtf((float)(f_cnt[g] + 1));
        f_p[g] = make_float2(dinv * xl0, dinv * xl1);
    }
    __syncthreads();
    for (long i = tid; i < (long)T*E; i += nt) {
        int t = (int)(i / E), e = (int)(i - (long)t*E);
        const int* et2 = ei + (size_t)t*2*E;
        int src = et2[e], dst = et2[E + e];
        float2 p = f_p[t*N + src];
        atomicAdd(&f_acc[2*(t*N + dst)],   p.x);
        atomicAdd(&f_acc[2*(t*N + dst)+1], p.y);
    }
    __syncthreads();
    for (int g = tid; g < TN; g += nt) {
        float dinv = rsqrtf((float)(f_cnt[g] + 1));
        float2 p = f_p[g];
        float g0 = fmaf(dinv, f_acc[2*g]   + p.x, bg[0]);
        float g1 = fmaf(dinv, f_acc[2*g+1] + p.y, bg[1]);
        f_u[3*g]   = fmaf(Wih[0], g0, fmaf(Wih[1], g1, bih[0] + bhh[0]));
        f_u[3*g+1] = fmaf(Wih[2], g0, fmaf(Wih[3], g1, bih[1] + bhh[1]));
        f_u[3*g+2] = fmaf(Wih[4], g0, fmaf(Wih[5], g1, bih[2] + bhh[2]));
    }
    __syncthreads();
    for (int g = tid; g < TN; g += nt) { f_cnt[g] = 0; f_acc[2*g] = 0.f; f_acc[2*g+1] = 0.f; }
    __syncthreads();
    if (tid == 0) {
        float h0 = 0.f, h1 = 0.f, h2 = 0.f;
        for (int k = 0; k < TN; k++) STEPM(f_u[3*k], f_u[3*k+1], f_u[3*k+2]);
        h0 = fmaxf(h0, 0.f); h1 = fmaxf(h1, 0.f); h2 = fmaxf(h2, 0.f);
        float z = fmaf(Wlin[0], h0, fmaf(Wlin[1], h1, fmaf(Wlin[2], h2, blin[0])));
        out[0] = 1.0f / (1.0f + expf(-z));
    }
}

extern "C" void kernel_launch(void* const* d_in, const int* in_sizes, int n_in,
                              void* d_out, int out_size) {
    const float* x    = (const float*)d_in[0];
    const int*   ei   = (const int*)  d_in[1];   // int32
    const float* Wg   = (const float*)d_in[2];
    const float* bg   = (const float*)d_in[3];
    const float* Wih  = (const float*)d_in[4];
    const float* Whh  = (const float*)d_in[5];
    const float* bih  = (const float*)d_in[6];
    const float* bhh  = (const float*)d_in[7];
    const float* Wlin = (const float*)d_in[8];
    const float* blin = (const float*)d_in[9];
    float* out = (float*)d_out;

    k_deg7 <<<XL_BLOCKS + DEG_BLOCKS, 256>>>(x, Wg, ei);
    k_msg7 <<<DEG_BLOCKS, 256>>>(ei);
    k_finish<<<1, 1024>>>(x, ei, Wg, bg, Wih, Whh, bih, bhh, Wlin, blin, out);
}

// round 15
// speedup vs baseline: 1.9772x; 1.3174x over previous
#include <cuda_runtime.h>
#include <math.h>

#define T 8
#define N 20000
#define E 1280000
#define TN (T*N)

#define TAILN  1280
#define CHUNKS 64
#define CLEN   20          // CHUNKS*CLEN == TAILN ; multiple of 4
#define WARMA  160         // tier-A warmup (multiple of 4)
#define WARMB  320         // tier-B warmup — passed the 2e-5 gate in round 14
#define WARMC  640         // tier-C warmup — proven safe since round 5
#define KEEP   (TAILN + WARMC)  // 1920 tail nodes of graph 7 need u
#define NODE0  (N - KEEP)       // 18080

#define K_SCALE 2.8853900817779268f   // 2*log2(e)

#define XL_BLOCKS  ((N + 255) / 256)   // 79
#define DEG_BLOCKS (E/8/256)           // 625 (exact)

// ---- cheap-path scratch (graph 7 only); self-cleaning across graph replays ----
__device__ float  d_xl[N*2];      // xl (fully overwritten each launch)
__device__ int    d_cnt4[4*N];    // 4-replica degree counts (zeroed in k_finish)
__device__ float  d_acc[KEEP*2];  // tail accumulator (zeroed in k_finish)
__device__ float  d_u0[KEEP], d_u1[KEEP], d_u2[KEEP];  // U = K*(u + rowsum(Whh))

// ---- fallback scratch (full problem; zeroed at fallback start) ----
__device__ int    f_cnt[TN];
__device__ float2 f_p[TN];
__device__ float  f_acc[TN*2];
__device__ float  f_u[TN*3];

__device__ __forceinline__ int cnt_of(int n) {
    return d_cnt4[n] + d_cnt4[N + n] + d_cnt4[2*N + n] + d_cnt4[3*N + n];
}

// ---------------- graph-7 xl + replicated degree histogram (fused) ----------------
__global__ void k_deg7(const float* __restrict__ x, const float* __restrict__ Wg,
                       const int* __restrict__ ei) {
    int b = blockIdx.x;
    if (b < XL_BLOCKS) {
        int n = b * 256 + threadIdx.x;
        if (n >= N) return;
        float x0 = x[2*(7*N + n)], x1 = x[2*(7*N + n) + 1];
        d_xl[2*n]   = fmaf(x0, Wg[0], x1 * Wg[1]);
        d_xl[2*n+1] = fmaf(x0, Wg[2], x1 * Wg[3]);
    } else {
        int idx = (b - XL_BLOCKS) * 256 + threadIdx.x;   // < E/8 exactly
        int rep = (threadIdx.x & 3) * N;                 // replica base
        const int* dp = ei + (size_t)7*2*E + E + 8*idx;
        int4 a = *reinterpret_cast<const int4*>(dp);
        int4 c = *reinterpret_cast<const int4*>(dp + 4);
        atomicAdd(&d_cnt4[rep + a.x], 1); atomicAdd(&d_cnt4[rep + a.y], 1);
        atomicAdd(&d_cnt4[rep + a.z], 1); atomicAdd(&d_cnt4[rep + a.w], 1);
        atomicAdd(&d_cnt4[rep + c.x], 1); atomicAdd(&d_cnt4[rep + c.y], 1);
        atomicAdd(&d_cnt4[rep + c.z], 1); atomicAdd(&d_cnt4[rep + c.w], 1);
    }
}

// ---------------- messages into the tail; dinv[src] from merged replicas ----------------
__device__ __forceinline__ void red2(float* p, float a, float b) {
    asm volatile("red.global.add.v2.f32 [%0], {%1, %2};"
                 :: "l"(p), "f"(a), "f"(b) : "memory");
}

__global__ void k_msg7(const int* __restrict__ ei) {
    int idx = blockIdx.x * blockDim.x + threadIdx.x;    // < E/8 exactly
    const int* eit = ei + (size_t)7*2*E;
    int4 s0 = *reinterpret_cast<const int4*>(eit + 8*idx);
    int4 s1 = *reinterpret_cast<const int4*>(eit + 8*idx + 4);
    int4 t0 = *reinterpret_cast<const int4*>(eit + E + 8*idx);
    int4 t1 = *reinterpret_cast<const int4*>(eit + E + 8*idx + 4);
    #define EDGE(S, D) if ((D) >= NODE0) { \
        float di = rsqrtf((float)(cnt_of(S) + 1)); \
        float2 xl = *reinterpret_cast<const float2*>(d_xl + 2*(S)); \
        red2(d_acc + 2*((D) - NODE0), di*xl.x, di*xl.y); }
    EDGE(s0.x, t0.x) EDGE(s0.y, t0.y) EDGE(s0.z, t0.z) EDGE(s0.w, t0.w)
    EDGE(s1.x, t1.x) EDGE(s1.y, t1.y) EDGE(s1.z, t1.z) EDGE(s1.w, t1.w)
    #undef EDGE
}

// ---------------- scan helpers (r-space: r = (1-h)/2, h = 1-2r) ----------------
// r' = rcp(ex2(A)+1), A = U + m00*r0 + m01*r1 + m02*r2 ; m = -2*K_SCALE*Whh
#define STEPR(c0, c1, c2) { \
    float A0 = fmaf(m00,r0, fmaf(m01,r1, fmaf(m02,r2, (c0)))); \
    float A1 = fmaf(m10,r0, fmaf(m11,r1, fmaf(m12,r2, (c1)))); \
    float A2 = fmaf(m20,r0, fmaf(m21,r1, fmaf(m22,r2, (c2)))); \
    float e0, e1, e2, q0, q1, q2; \
    asm("ex2.approx.f32 %0, %1;" : "=f"(e0) : "f"(A0)); \
    asm("ex2.approx.f32 %0, %1;" : "=f"(e1) : "f"(A1)); \
    asm("ex2.approx.f32 %0, %1;" : "=f"(e2) : "f"(A2)); \
    e0 += 1.0f; e1 += 1.0f; e2 += 1.0f; \
    asm("rcp.approx.f32 %0, %1;" : "=f"(q0) : "f"(e0)); \
    asm("rcp.approx.f32 %0, %1;" : "=f"(q1) : "f"(e1)); \
    asm("rcp.approx.f32 %0, %1;" : "=f"(q2) : "f"(e2)); \
    r0 = q0; r1 = q1; r2 = q2; }

#define QUADR(k) { \
    float4 a = *reinterpret_cast<const float4*>(d_u0 + (k)); \
    float4 b = *reinterpret_cast<const float4*>(d_u1 + (k)); \
    float4 u = *reinterpret_cast<const float4*>(d_u2 + (k)); \
    STEPR(a.x, b.x, u.x); STEPR(a.y, b.y, u.y); \
    STEPR(a.z, b.z, u.z); STEPR(a.w, b.w, u.w); }

// fallback step (unscaled, exact formulation)
__device__ __forceinline__ float tanh_fast(float x) {
    float e = __expf(2.0f * x);
    return 1.0f - __fdividef(2.0f, e + 1.0f);
}
#define STEPM(c0, c1, c2) { \
    float a0 = fmaf(v00,h0, fmaf(v01,h1, fmaf(v02,h2, (c0)))); \
    float a1 = fmaf(v10,h0, fmaf(v11,h1, fmaf(v12,h2, (c1)))); \
    float a2 = fmaf(v20,h0, fmaf(v21,h1, fmaf(v22,h2, (c2)))); \
    h0 = tanh_fast(a0); h1 = tanh_fast(a1); h2 = tanh_fast(a2); }

// ---------------- u-prep + three-tier scan + gate + output (+ full fallback) ----------------
__global__ void k_finish(const float* __restrict__ x, const int* __restrict__ ei,
                         const float* __restrict__ Wg, const float* __restrict__ bg,
                         const float* __restrict__ Wih, const float* __restrict__ Whh,
                         const float* __restrict__ bih, const float* __restrict__ bhh,
                         const float* __restrict__ Wlin, const float* __restrict__ blin,
                         float* __restrict__ out) {
    __shared__ float s_s[CHUNKS+2][3], s_b[CHUNKS][3];   // stored as h
    __shared__ float s_md[2];
    __shared__ int s_ok;
    int tid = threadIdx.x;
    int nt = blockDim.x;

    // ---- phase A: U = K_SCALE*(u + rowsum(Whh)) for the tail nodes ----
    {
        float wg0=Wih[0], wg1=Wih[1], wg2=Wih[2], wg3=Wih[3], wg4=Wih[4], wg5=Wih[5];
        float rs0 = Whh[0]+Whh[1]+Whh[2], rs1 = Whh[3]+Whh[4]+Whh[5], rs2 = Whh[6]+Whh[7]+Whh[8];
        float c0 = bih[0] + bhh[0] + rs0, c1 = bih[1] + bhh[1] + rs1, c2 = bih[2] + bhh[2] + rs2;
        float bg0 = bg[0], bg1 = bg[1];
        for (int i = tid; i < KEEP; i += nt) {
            int n = NODE0 + i;
            float dinv = rsqrtf((float)(cnt_of(n) + 1));
            float2 xl = *reinterpret_cast<const float2*>(d_xl + 2*n);
            float g0 = fmaf(dinv, fmaf(dinv, xl.x, d_acc[2*i]),   bg0);
            float g1 = fmaf(dinv, fmaf(dinv, xl.y, d_acc[2*i+1]), bg1);
            d_u0[i] = K_SCALE * fmaf(wg0, g0, fmaf(wg1, g1, c0));
            d_u1[i] = K_SCALE * fmaf(wg2, g0, fmaf(wg3, g1, c1));
            d_u2[i] = K_SCALE * fmaf(wg4, g0, fmaf(wg5, g1, c2));
        }
    }
    __syncthreads();

    // ---- phase B: three-tier chunk scan (warmup 160 / 320 / 640) ----
    float m00=-2.f*K_SCALE*Whh[0], m01=-2.f*K_SCALE*Whh[1], m02=-2.f*K_SCALE*Whh[2];
    float m10=-2.f*K_SCALE*Whh[3], m11=-2.f*K_SCALE*Whh[4], m12=-2.f*K_SCALE*Whh[5];
    float m20=-2.f*K_SCALE*Whh[6], m21=-2.f*K_SCALE*Whh[7], m22=-2.f*K_SCALE*Whh[8];

    for (int tier = 0; tier < 3; tier++) {
        int warm = (tier == 0) ? WARMA : (tier == 1) ? WARMB : WARMC;
        if (tid < CHUNKS + 2) {
            int c = (tid < CHUNKS) ? tid : 0;
            int k0 = WARMC + c * CLEN;      // chunk entry (fixed grid, multiple of 4)
            int ws = k0 - warm;             // multiple of 4
            // h=0 -> r=0.5 ; h=+1 -> r=0 ; h=-1 -> r=1
            float init = (tid == CHUNKS) ? 0.f : (tid == CHUNKS+1 ? 1.f : 0.5f);
            float r0 = init, r1 = init, r2 = init;
            for (int k = ws; k < k0; k += 4) QUADR(k);
            s_s[tid][0] = fmaf(-2.f, r0, 1.f);
            s_s[tid][1] = fmaf(-2.f, r1, 1.f);
            s_s[tid][2] = fmaf(-2.f, r2, 1.f);
            if (tid < CHUNKS) {
                #pragma unroll 5
                for (int k = k0; k < k0 + CLEN; k += 4) QUADR(k);
                s_b[tid][0] = fmaf(-2.f, r0, 1.f);
                s_b[tid][1] = fmaf(-2.f, r1, 1.f);
                s_b[tid][2] = fmaf(-2.f, r2, 1.f);
            }
        } else if (tid >= 128 && tier == 0) {
            // self-clean scratch, hidden under the tier-0 scan
            int t2 = tid - 128, n2 = nt - 128;
            for (int g = t2; g < 4*N;    g += n2) d_cnt4[g] = 0;
            for (int g = t2; g < KEEP*2; g += n2) d_acc[g] = 0.f;
        }
        __syncthreads();

        // parallel gate: threads 0..CHUNKS-1 check boundaries, plus entrance checks
        if (tid < CHUNKS) {
            float lm = 0.f;
            if (tid >= 1) {
                for (int m = 0; m < 3; m++)
                    lm = fmaxf(lm, fabsf(s_s[tid][m] - s_b[tid-1][m]));
            } else {
                for (int m = 0; m < 3; m++) {       // entrance insensitivity
                    lm = fmaxf(lm, fabsf(s_s[CHUNKS][m]   - s_s[0][m]));
                    lm = fmaxf(lm, fabsf(s_s[CHUNKS+1][m] - s_s[0][m]));
                }
            }
            #pragma unroll
            for (int o = 16; o; o >>= 1)
                lm = fmaxf(lm, __shfl_xor_sync(0xffffffff, lm, o));
            if ((tid & 31) == 0) s_md[tid >> 5] = lm;
        }
        __syncthreads();

        if (tid == 0) {
            float md = fmaxf(s_md[0], s_md[1]);
            s_ok = (md < 2e-5f);
            if (s_ok) {
                float h0 = fmaxf(s_b[CHUNKS-1][0], 0.f);
                float h1 = fmaxf(s_b[CHUNKS-1][1], 0.f);
                float h2 = fmaxf(s_b[CHUNKS-1][2], 0.f);
                float z = fmaf(Wlin[0], h0, fmaf(Wlin[1], h1, fmaf(Wlin[2], h2, blin[0])));
                out[0] = 1.0f / (1.0f + expf(-z));
            }
        }
        __syncthreads();
        if (s_ok) return;
    }

    // ================= FALLBACK: exact full computation =================
    float v00=Whh[0], v01=Whh[1], v02=Whh[2];
    float v10=Whh[3], v11=Whh[4], v12=Whh[5];
    float v20=Whh[6], v21=Whh[7], v22=Whh[8];
    for (int g = tid; g < TN; g += nt) { f_cnt[g] = 0; f_acc[2*g] = 0.f; f_acc[2*g+1] = 0.f; }
    __syncthreads();
    for (long i = tid; i < (long)T*E; i += nt) {
        int t = (int)(i / E), e = (int)(i - (long)t*E);
        int dst = ei[(size_t)t*2*E + E + e];
        atomicAdd(&f_cnt[t*N + dst], 1);
    }
    __syncthreads();
    for (int g = tid; g < TN; g += nt) {
        float x0 = x[2*g], x1 = x[2*g+1];
        float xl0 = fmaf(x0, Wg[0], x1*Wg[1]);
        float xl1 = fmaf(x0, Wg[2], x1*Wg[3]);
        float dinv = rsqrtf((float)(f_cnt[g] + 1));
        f_p[g] = make_float2(dinv * xl0, dinv * xl1);
    }
    __syncthreads();
    for (long i = tid; i < (long)T*E; i += nt) {
        int t = (int)(i / E), e = (int)(i - (long)t*E);
        const int* et2 = ei + (size_t)t*2*E;
        int src = et2[e], dst = et2[E + e];
        float2 p = f_p[t*N + src];
        atomicAdd(&f_acc[2*(t*N + dst)],   p.x);
        atomicAdd(&f_acc[2*(t*N + dst)+1], p.y);
    }
    __syncthreads();
    for (int g = tid; g < TN; g += nt) {
        float dinv = rsqrtf((float)(f_cnt[g] + 1));
        float2 p = f_p[g];
        float g0 = fmaf(dinv, f_acc[2*g]   + p.x, bg[0]);
        float g1 = fmaf(dinv, f_acc[2*g+1] + p.y, bg[1]);
        f_u[3*g]   = fmaf(Wih[0], g0, fmaf(Wih[1], g1, bih[0] + bhh[0]));
        f_u[3*g+1] = fmaf(Wih[2], g0, fmaf(Wih[3], g1, bih[1] + bhh[1]));
        f_u[3*g+2] = fmaf(Wih[4], g0, fmaf(Wih[5], g1, bih[2] + bhh[2]));
    }
    __syncthreads();
    for (int g = tid; g < TN; g += nt) { f_cnt[g] = 0; f_acc[2*g] = 0.f; f_acc[2*g+1] = 0.f; }
    __syncthreads();
    if (tid == 0) {
        float h0 = 0.f, h1 = 0.f, h2 = 0.f;
        for (int k = 0; k < TN; k++) STEPM(f_u[3*k], f_u[3*k+1], f_u[3*k+2]);
        h0 = fmaxf(h0, 0.f); h1 = fmaxf(h1, 0.f); h2 = fmaxf(h2, 0.f);
        float z = fmaf(Wlin[0], h0, fmaf(Wlin[1], h1, fmaf(Wlin[2], h2, blin[0])));
        out[0] = 1.0f / (1.0f + expf(-z));
    }
}

extern "C" void kernel_launch(void* const* d_in, const int* in_sizes, int n_in,
                              void* d_out, int out_size) {
    const float* x    = (const float*)d_in[0];
    const int*   ei   = (const int*)  d_in[1];   // int32
    const float* Wg   = (const float*)d_in[2];
    const float* bg   = (const float*)d_in[3];
    const float* Wih  = (const float*)d_in[4];
    const float* Whh  = (const float*)d_in[5];
    const float* bih  = (const float*)d_in[6];
    const float* bhh  = (const float*)d_in[7];
    const float* Wlin = (const float*)d_in[8];
    const float* blin = (const float*)d_in[9];
    float* out = (float*)d_out;

    k_deg7 <<<XL_BLOCKS + DEG_BLOCKS, 256>>>(x, Wg, ei);
    k_msg7 <<<DEG_BLOCKS, 256>>>(ei);
    k_finish<<<1, 1024>>>(x, ei, Wg, bg, Wih, Whh, bih, bhh, Wlin, blin, out);
}

// round 16
// speedup vs baseline: 2.3339x; 1.1804x over previous
#include <cuda_runtime.h>
#include <math.h>

#define T 8
#define N 20000
#define E 1280000
#define TN (T*N)

#define TAILN  1280
#define CHUNKS 64
#define CLEN   20          // CHUNKS*CLEN == TAILN ; multiple of 4
#define WARM0  80          // tier 0 (new)
#define WARM1  160         // tier 1 — passed gate in round 15
#define WARM2  320         // tier 2 — passed gate in round 14
#define WARM3  640         // tier 3 — proven safe since round 5
#define NTIERS 4
#define KEEP   (TAILN + WARM3)  // 1920 tail nodes of graph 7 need u
#define NODE0  (N - KEEP)       // 18080

#define K_SCALE 2.8853900817779268f   // 2*log2(e)

#define XL_BLOCKS  ((N + 255) / 256)   // 79
#define DEG_BLOCKS (E/8/256)           // 625 (exact)

// ---- cheap-path scratch (graph 7 only); self-cleaning across graph replays ----
__device__ float  d_xl[N*2];      // xl (fully overwritten each launch)
__device__ int    d_cnt4[4*N];    // 4-replica degree counts (zeroed in k_finish)
__device__ float  d_acc[KEEP*2];  // tail accumulator (zeroed in k_finish)
__device__ float  d_u0[KEEP], d_u1[KEEP], d_u2[KEEP];  // U = K*(u + rowsum(Whh))

// ---- fallback scratch (full problem; zeroed at fallback start) ----
__device__ int    f_cnt[TN];
__device__ float2 f_p[TN];
__device__ float  f_acc[TN*2];
__device__ float  f_u[TN*3];

__device__ __forceinline__ int cnt_of(int n) {
    return d_cnt4[n] + d_cnt4[N + n] + d_cnt4[2*N + n] + d_cnt4[3*N + n];
}

// ---------------- graph-7 xl + replicated degree histogram (fused) ----------------
__global__ void k_deg7(const float* __restrict__ x, const float* __restrict__ Wg,
                       const int* __restrict__ ei) {
    int b = blockIdx.x;
    if (b < XL_BLOCKS) {
        int n = b * 256 + threadIdx.x;
        if (n >= N) return;
        float x0 = x[2*(7*N + n)], x1 = x[2*(7*N + n) + 1];
        d_xl[2*n]   = fmaf(x0, Wg[0], x1 * Wg[1]);
        d_xl[2*n+1] = fmaf(x0, Wg[2], x1 * Wg[3]);
    } else {
        int idx = (b - XL_BLOCKS) * 256 + threadIdx.x;   // < E/8 exactly
        int rep = (threadIdx.x & 3) * N;                 // replica base
        const int* dp = ei + (size_t)7*2*E + E + 8*idx;
        int4 a = *reinterpret_cast<const int4*>(dp);
        int4 c = *reinterpret_cast<const int4*>(dp + 4);
        atomicAdd(&d_cnt4[rep + a.x], 1); atomicAdd(&d_cnt4[rep + a.y], 1);
        atomicAdd(&d_cnt4[rep + a.z], 1); atomicAdd(&d_cnt4[rep + a.w], 1);
        atomicAdd(&d_cnt4[rep + c.x], 1); atomicAdd(&d_cnt4[rep + c.y], 1);
        atomicAdd(&d_cnt4[rep + c.z], 1); atomicAdd(&d_cnt4[rep + c.w], 1);
    }
}

// ---------------- messages into the tail; dinv[src] from merged replicas ----------------
__device__ __forceinline__ void red2(float* p, float a, float b) {
    asm volatile("red.global.add.v2.f32 [%0], {%1, %2};"
                 :: "l"(p), "f"(a), "f"(b) : "memory");
}

__global__ void k_msg7(const int* __restrict__ ei) {
    int idx = blockIdx.x * blockDim.x + threadIdx.x;    // < E/8 exactly
    const int* eit = ei + (size_t)7*2*E;
    int4 s0 = *reinterpret_cast<const int4*>(eit + 8*idx);
    int4 s1 = *reinterpret_cast<const int4*>(eit + 8*idx + 4);
    int4 t0 = *reinterpret_cast<const int4*>(eit + E + 8*idx);
    int4 t1 = *reinterpret_cast<const int4*>(eit + E + 8*idx + 4);
    #define EDGE(S, D) if ((D) >= NODE0) { \
        float di = rsqrtf((float)(cnt_of(S) + 1)); \
        float2 xl = *reinterpret_cast<const float2*>(d_xl + 2*(S)); \
        red2(d_acc + 2*((D) - NODE0), di*xl.x, di*xl.y); }
    EDGE(s0.x, t0.x) EDGE(s0.y, t0.y) EDGE(s0.z, t0.z) EDGE(s0.w, t0.w)
    EDGE(s1.x, t1.x) EDGE(s1.y, t1.y) EDGE(s1.z, t1.z) EDGE(s1.w, t1.w)
    #undef EDGE
}

// ---------------- scan helpers (r-space: r = (1-h)/2, h = 1-2r) ----------------
// r' = rcp(ex2(A)+1), A = U + m00*r0 + m01*r1 + m02*r2 ; m = -2*K_SCALE*Whh
#define STEPR(c0, c1, c2) { \
    float A0 = fmaf(m00,r0, fmaf(m01,r1, fmaf(m02,r2, (c0)))); \
    float A1 = fmaf(m10,r0, fmaf(m11,r1, fmaf(m12,r2, (c1)))); \
    float A2 = fmaf(m20,r0, fmaf(m21,r1, fmaf(m22,r2, (c2)))); \
    float e0, e1, e2, q0, q1, q2; \
    asm("ex2.approx.f32 %0, %1;" : "=f"(e0) : "f"(A0)); \
    asm("ex2.approx.f32 %0, %1;" : "=f"(e1) : "f"(A1)); \
    asm("ex2.approx.f32 %0, %1;" : "=f"(e2) : "f"(A2)); \
    e0 += 1.0f; e1 += 1.0f; e2 += 1.0f; \
    asm("rcp.approx.f32 %0, %1;" : "=f"(q0) : "f"(e0)); \
    asm("rcp.approx.f32 %0, %1;" : "=f"(q1) : "f"(e1)); \
    asm("rcp.approx.f32 %0, %1;" : "=f"(q2) : "f"(e2)); \
    r0 = q0; r1 = q1; r2 = q2; }

#define QUADR(k) { \
    float4 a = *reinterpret_cast<const float4*>(d_u0 + (k)); \
    float4 b = *reinterpret_cast<const float4*>(d_u1 + (k)); \
    float4 u = *reinterpret_cast<const float4*>(d_u2 + (k)); \
    STEPR(a.x, b.x, u.x); STEPR(a.y, b.y, u.y); \
    STEPR(a.z, b.z, u.z); STEPR(a.w, b.w, u.w); }

// fallback step (unscaled, exact formulation)
__device__ __forceinline__ float tanh_fast(float x) {
    float e = __expf(2.0f * x);
    return 1.0f - __fdividef(2.0f, e + 1.0f);
}
#define STEPM(c0, c1, c2) { \
    float a0 = fmaf(v00,h0, fmaf(v01,h1, fmaf(v02,h2, (c0)))); \
    float a1 = fmaf(v10,h0, fmaf(v11,h1, fmaf(v12,h2, (c1)))); \
    float a2 = fmaf(v20,h0, fmaf(v21,h1, fmaf(v22,h2, (c2)))); \
    h0 = tanh_fast(a0); h1 = tanh_fast(a1); h2 = tanh_fast(a2); }

// ---------------- u-prep + four-tier scan + gate + output (+ full fallback) ----------------
__global__ void k_finish(const float* __restrict__ x, const int* __restrict__ ei,
                         const float* __restrict__ Wg, const float* __restrict__ bg,
                         const float* __restrict__ Wih, const float* __restrict__ Whh,
                         const float* __restrict__ bih, const float* __restrict__ bhh,
                         const float* __restrict__ Wlin, const float* __restrict__ blin,
                         float* __restrict__ out) {
    __shared__ float s_s[CHUNKS+2][3], s_b[CHUNKS][3];   // stored as h
    __shared__ float s_md[2];
    __shared__ int s_ok;
    int tid = threadIdx.x;
    int nt = blockDim.x;

    // ---- phase A: U = K_SCALE*(u + rowsum(Whh)) for the tail nodes ----
    {
        float wg0=Wih[0], wg1=Wih[1], wg2=Wih[2], wg3=Wih[3], wg4=Wih[4], wg5=Wih[5];
        float rs0 = Whh[0]+Whh[1]+Whh[2], rs1 = Whh[3]+Whh[4]+Whh[5], rs2 = Whh[6]+Whh[7]+Whh[8];
        float c0 = bih[0] + bhh[0] + rs0, c1 = bih[1] + bhh[1] + rs1, c2 = bih[2] + bhh[2] + rs2;
        float bg0 = bg[0], bg1 = bg[1];
        for (int i = tid; i < KEEP; i += nt) {
            int n = NODE0 + i;
            float dinv = rsqrtf((float)(cnt_of(n) + 1));
            float2 xl = *reinterpret_cast<const float2*>(d_xl + 2*n);
            float g0 = fmaf(dinv, fmaf(dinv, xl.x, d_acc[2*i]),   bg0);
            float g1 = fmaf(dinv, fmaf(dinv, xl.y, d_acc[2*i+1]), bg1);
            d_u0[i] = K_SCALE * fmaf(wg0, g0, fmaf(wg1, g1, c0));
            d_u1[i] = K_SCALE * fmaf(wg2, g0, fmaf(wg3, g1, c1));
            d_u2[i] = K_SCALE * fmaf(wg4, g0, fmaf(wg5, g1, c2));
        }
    }
    __syncthreads();

    // ---- phase B: four-tier chunk scan (warmup 80 / 160 / 320 / 640) ----
    float m00=-2.f*K_SCALE*Whh[0], m01=-2.f*K_SCALE*Whh[1], m02=-2.f*K_SCALE*Whh[2];
    float m10=-2.f*K_SCALE*Whh[3], m11=-2.f*K_SCALE*Whh[4], m12=-2.f*K_SCALE*Whh[5];
    float m20=-2.f*K_SCALE*Whh[6], m21=-2.f*K_SCALE*Whh[7], m22=-2.f*K_SCALE*Whh[8];

    const int warms[NTIERS] = {WARM0, WARM1, WARM2, WARM3};
    for (int tier = 0; tier < NTIERS; tier++) {
        int warm = warms[tier];
        if (tid < CHUNKS + 2) {
            int c = (tid < CHUNKS) ? tid : 0;
            int k0 = WARM3 + c * CLEN;      // chunk entry (fixed grid, multiple of 4)
            int ws = k0 - warm;             // multiple of 4
            // h=0 -> r=0.5 ; h=+1 -> r=0 ; h=-1 -> r=1
            float init = (tid == CHUNKS) ? 0.f : (tid == CHUNKS+1 ? 1.f : 0.5f);
            float r0 = init, r1 = init, r2 = init;
            for (int k = ws; k < k0; k += 4) QUADR(k);
            s_s[tid][0] = fmaf(-2.f, r0, 1.f);
            s_s[tid][1] = fmaf(-2.f, r1, 1.f);
            s_s[tid][2] = fmaf(-2.f, r2, 1.f);
            if (tid < CHUNKS) {
                #pragma unroll 5
                for (int k = k0; k < k0 + CLEN; k += 4) QUADR(k);
                s_b[tid][0] = fmaf(-2.f, r0, 1.f);
                s_b[tid][1] = fmaf(-2.f, r1, 1.f);
                s_b[tid][2] = fmaf(-2.f, r2, 1.f);
            }
        } else if (tid >= 128 && tier == 0) {
            // self-clean scratch, hidden under the tier-0 scan
            int t2 = tid - 128, n2 = nt - 128;
            for (int g = t2; g < 4*N;    g += n2) d_cnt4[g] = 0;
            for (int g = t2; g < KEEP*2; g += n2) d_acc[g] = 0.f;
        }
        __syncthreads();

        // parallel gate: threads 0..CHUNKS-1 check boundaries + entrance variants
        if (tid < CHUNKS) {
            float lm = 0.f;
            if (tid >= 1) {
                for (int m = 0; m < 3; m++)
                    lm = fmaxf(lm, fabsf(s_s[tid][m] - s_b[tid-1][m]));
            } else {
                for (int m = 0; m < 3; m++) {       // entrance insensitivity
                    lm = fmaxf(lm, fabsf(s_s[CHUNKS][m]   - s_s[0][m]));
                    lm = fmaxf(lm, fabsf(s_s[CHUNKS+1][m] - s_s[0][m]));
                }
            }
            #pragma unroll
            for (int o = 16; o; o >>= 1)
                lm = fmaxf(lm, __shfl_xor_sync(0xffffffff, lm, o));
            if ((tid & 31) == 0) s_md[tid >> 5] = lm;
        }
        __syncthreads();

        if (tid == 0) {
            float md = fmaxf(s_md[0], s_md[1]);
            s_ok = (md < 2e-5f);
            if (s_ok) {
                float h0 = fmaxf(s_b[CHUNKS-1][0], 0.f);
                float h1 = fmaxf(s_b[CHUNKS-1][1], 0.f);
                float h2 = fmaxf(s_b[CHUNKS-1][2], 0.f);
                float z = fmaf(Wlin[0], h0, fmaf(Wlin[1], h1, fmaf(Wlin[2], h2, blin[0])));
                out[0] = 1.0f / (1.0f + expf(-z));
            }
        }
        __syncthreads();
        if (s_ok) return;
    }

    // ================= FALLBACK: exact full computation =================
    float v00=Whh[0], v01=Whh[1], v02=Whh[2];
    float v10=Whh[3], v11=Whh[4], v12=Whh[5];
    float v20=Whh[6], v21=Whh[7], v22=Whh[8];
    for (int g = tid; g < TN; g += nt) { f_cnt[g] = 0; f_acc[2*g] = 0.f; f_acc[2*g+1] = 0.f; }
    __syncthreads();
    for (long i = tid; i < (long)T*E; i += nt) {
        int t = (int)(i / E), e = (int)(i - (long)t*E);
        int dst = ei[(size_t)t*2*E + E + e];
        atomicAdd(&f_cnt[t*N + dst], 1);
    }
    __syncthreads();
    for (int g = tid; g < TN; g += nt) {
        float x0 = x[2*g], x1 = x[2*g+1];
        float xl0 = fmaf(x0, Wg[0], x1*Wg[1]);
        float xl1 = fmaf(x0, Wg[2], x1*Wg[3]);
        float dinv = rsqrtf((float)(f_cnt[g] + 1));
        f_p[g] = make_float2(dinv * xl0, dinv * xl1);
    }
    __syncthreads();
    for (long i = tid; i < (long)T*E; i += nt) {
        int t = (int)(i / E), e = (int)(i - (long)t*E);
        const int* et2 = ei + (size_t)t*2*E;
        int src = et2[e], dst = et2[E + e];
        float2 p = f_p[t*N + src];
        atomicAdd(&f_acc[2*(t*N + dst)],   p.x);
        atomicAdd(&f_acc[2*(t*N + dst)+1], p.y);
    }
    __syncthreads();
    for (int g = tid; g < TN; g += nt) {
        float dinv = rsqrtf((float)(f_cnt[g] + 1));
        float2 p = f_p[g];
        float g0 = fmaf(dinv, f_acc[2*g]   + p.x, bg[0]);
        float g1 = fmaf(dinv, f_acc[2*g+1] + p.y, bg[1]);
        f_u[3*g]   = fmaf(Wih[0], g0, fmaf(Wih[1], g1, bih[0] + bhh[0]));
        f_u[3*g+1] = fmaf(Wih[2], g0, fmaf(Wih[3], g1, bih[1] + bhh[1]));
        f_u[3*g+2] = fmaf(Wih[4], g0, fmaf(Wih[5], g1, bih[2] + bhh[2]));
    }
    __syncthreads();
    for (int g = tid; g < TN; g += nt) { f_cnt[g] = 0; f_acc[2*g] = 0.f; f_acc[2*g+1] = 0.f; }
    __syncthreads();
    if (tid == 0) {
        float h0 = 0.f, h1 = 0.f, h2 = 0.f;
        for (int k = 0; k < TN; k++) STEPM(f_u[3*k], f_u[3*k+1], f_u[3*k+2]);
        h0 = fmaxf(h0, 0.f); h1 = fmaxf(h1, 0.f); h2 = fmaxf(h2, 0.f);
        float z = fmaf(Wlin[0], h0, fmaf(Wlin[1], h1, fmaf(Wlin[2], h2, blin[0])));
        out[0] = 1.0f / (1.0f + expf(-z));
    }
}

extern "C" void kernel_launch(void* const* d_in, const int* in_sizes, int n_in,
                              void* d_out, int out_size) {
    const float* x    = (const float*)d_in[0];
    const int*   ei   = (const int*)  d_in[1];   // int32
    const float* Wg   = (const float*)d_in[2];
    const float* bg   = (const float*)d_in[3];
    const float* Wih  = (const float*)d_in[4];
    const float* Whh  = (const float*)d_in[5];
    const float* bih  = (const float*)d_in[6];
    const float* bhh  = (const float*)d_in[7];
    const float* Wlin = (const float*)d_in[8];
    const float* blin = (const float*)d_in[9];
    float* out = (float*)d_out;

    k_deg7 <<<XL_BLOCKS + DEG_BLOCKS, 256>>>(x, Wg, ei);
    k_msg7 <<<DEG_BLOCKS, 256>>>(ei);
    k_finish<<<1, 1024>>>(x, ei, Wg, bg, Wih, Whh, bih, bhh, Wlin, blin, out);
}